// round 14
// baseline (speedup 1.0000x reference)
#include <cuda_runtime.h>
#include <cuda_fp16.h>
#include <cstdint>
#include <cstring>

// ---------------------------------------------------------------------------
// Problem constants
// ---------------------------------------------------------------------------
static constexpr int C      = 128;          // emb dim (GEMM K)
static constexpr int NCLS   = 128;          // classes (GEMM N)
static constexpr int HW     = 262144;       // spatial positions (GEMM M total)
static constexpr int K      = 131072;       // gathered rows
static constexpr int TILE_M = 128;
static constexpr int NTILES = HW / TILE_M;  // 2048
static constexpr int BCAP   = 16;           // bucket capacity (Poisson(0.5): overflow ~1e-21)
static constexpr int KCH    = 64;           // k-chunk (smem A staging)

// ---------------------------------------------------------------------------
// Device scratch (static — no runtime allocation)
// ---------------------------------------------------------------------------
__device__ int g_idx[K];                      // normalized int32 indices
__device__ int g_cnt[HW];                     // per-position multiplicity
__device__ int g_bucket[(size_t)HW * BCAP];   // inverted index (16 MB)
__device__ __align__(16) uint32_t g_WfHi[8192];  // W fp16 frags, lane-ordered

// ---------------------------------------------------------------------------
// Warp MMA: m16n8k16, fp16 x fp16 -> fp32  (arch-portable HMMA path)
// ---------------------------------------------------------------------------
__device__ __forceinline__ void mma16816(float* c, const uint32_t* a,
                                         uint32_t b0, uint32_t b1) {
    asm volatile(
        "mma.sync.aligned.m16n8k16.row.col.f32.f16.f16.f32 "
        "{%0,%1,%2,%3}, {%4,%5,%6,%7}, {%8,%9}, {%0,%1,%2,%3};"
        : "+f"(c[0]), "+f"(c[1]), "+f"(c[2]), "+f"(c[3])
        : "r"(a[0]), "r"(a[1]), "r"(a[2]), "r"(a[3]), "r"(b0), "r"(b1));
}

__device__ __forceinline__ uint32_t pack_hilo(float a) {
    // low 16 bits: fp16(a) ; high 16 bits: fp16(a - fp16(a))
    __half h = __float2half(a);
    float r = a - __half2float(h);
    __half l = __float2half(r);
    unsigned short hb, lb;
    memcpy(&hb, &h, 2);
    memcpy(&lb, &l, 2);
    return (uint32_t)hb | ((uint32_t)lb << 16);
}

// ---------------------------------------------------------------------------
// Kernel 1: zero counters + normalize index dtype (int64-or-int32) to int32
// ---------------------------------------------------------------------------
__global__ void zero_convert_kernel(const void* __restrict__ raw) {
    int t = blockIdx.x * 256 + threadIdx.x;      // HW threads
    g_cnt[t] = 0;
    if (t < K) {
        const int* i32 = (const int*)raw;
        bool is64 = true;
#pragma unroll
        for (int j = 0; j < 32; j++)
            if (i32[2 * j + 1] != 0) is64 = false;
        g_idx[t] = is64 ? i32[2 * t] : i32[t];
    }
}

// ---------------------------------------------------------------------------
// Kernel 2: scatter k into fixed-capacity buckets
// ---------------------------------------------------------------------------
__global__ void scatter_kernel() {
    int k = blockIdx.x * 256 + threadIdx.x;
    int p = g_idx[k];
    int s = atomicAdd(&g_cnt[p], 1);
    if (s < BCAP) g_bucket[(size_t)p * BCAP + s] = k;
}

// ---------------------------------------------------------------------------
// Kernel 3: W -> fp16 mma-fragment-ordered array (hi precision only).
// Entry t = ((kb*16+nb)*32 + lane)*2 + reg.
//   n = nb*8 + lane/4 ; k = kb*16 + (lane%4)*2 + reg*8 ; packs W[n][k],W[n][k+1]
// ---------------------------------------------------------------------------
__global__ void prepW_kernel(const float* __restrict__ W) {
    int t = blockIdx.x * 256 + threadIdx.x;      // 8192
    int r  = t & 1;
    int l  = (t >> 1) & 31;
    int f  = t >> 6;                              // kb*16+nb
    int kb = f >> 4, nb = f & 15;
    int n = nb * 8 + (l >> 2);
    int k = kb * 16 + (l & 3) * 2 + r * 8;
    __half h0 = __float2half(W[n * C + k]);
    __half h1 = __float2half(W[n * C + k + 1]);
    unsigned short h0b, h1b;
    memcpy(&h0b, &h0, 2); memcpy(&h1b, &h1, 2);
    g_WfHi[t] = (uint32_t)h0b | ((uint32_t)h1b << 16);
}

// ---------------------------------------------------------------------------
// Fused dense GEMM + softmax + inverted-gather epilogue.
// R7 mechanics (pre-packed A words, 2x64-ch chunks, bit-op fragment
// recombination, 8 warps x (16 m x 128 n)), but fp16 A-hi/lo vs fp16 B-hi:
// P = Ahi*Bh + Alo*Bh = A*Bh exactly -> 2 MMA passes, no WLO array.
// smem: A 33.8KB + W 32.8KB + bias = 67KB => 3 CTAs/SM (24 warps).
// ---------------------------------------------------------------------------
static constexpr int ASTR    = 132;                 // packed-word stride per k row
static constexpr int SM_AS   = 0;                   // 64*132*4 = 33792
static constexpr int SM_WHI  = 33792;               // 32768 -> 66560
static constexpr int SM_BIAS = 66560;               // 512   -> 67072
static constexpr int SM_TOTAL = 67072;

__global__ void __launch_bounds__(256, 3)
gemm_kernel(const float* __restrict__ gc,
            const float* __restrict__ bias,
            float* __restrict__ out) {
    extern __shared__ unsigned char smem[];
    uint32_t* AS = (uint32_t*)(smem + SM_AS);
    const uint2* WH = (const uint2*)(smem + SM_WHI);
    float* bs = (float*)(smem + SM_BIAS);

    int tid  = threadIdx.x;
    int lane = tid & 31;
    int warp = tid >> 5;
    int p0   = blockIdx.x * TILE_M;

    // Stage W fragment array + bias (covered by first __syncthreads)
    {
        const int4* shi = (const int4*)g_WfHi;           // 2048 int4
        int4* dhi = (int4*)(smem + SM_WHI);
#pragma unroll
        for (int i = 0; i < 8; i++)
            dhi[tid + i * 256] = shi[tid + i * 256];
        if (tid < NCLS) bs[tid] = bias[tid];
    }

    int mA = warp * 16 + (lane >> 2);
    int mB = mA + 8;

    float acc[16][4];
#pragma unroll
    for (int nb = 0; nb < 16; nb++)
#pragma unroll
        for (int j = 0; j < 4; j++) acc[nb][j] = 0.0f;

#pragma unroll
    for (int kh = 0; kh < 2; kh++) {
        // ---- Stage A chunk: channels [kh*64, kh*64+64), float4 coalesced ----
#pragma unroll
        for (int i = 0; i < 8; i++) {
            int e4 = tid + i * 256;                      // 2048 float4
            int c  = e4 >> 5;                            // 0..63
            int m  = (e4 & 31) * 4;
            float4 v = *(const float4*)(gc + (size_t)(kh * KCH + c) * HW + p0 + m);
            uint32_t* dst = AS + c * ASTR + m;
            dst[0] = pack_hilo(v.x);
            dst[1] = pack_hilo(v.y);
            dst[2] = pack_hilo(v.z);
            dst[3] = pack_hilo(v.w);
        }
        __syncthreads();

        // ---- MMA: 4 k16-blocks in this chunk ----
#pragma unroll
        for (int kb = 0; kb < 4; kb++) {
            int k0 = kb * 16 + (lane & 3) * 2;
            uint32_t u0 = AS[(k0    ) * ASTR + mA];
            uint32_t u1 = AS[(k0 + 1) * ASTR + mA];
            uint32_t u2 = AS[(k0 + 8) * ASTR + mA];
            uint32_t u3 = AS[(k0 + 9) * ASTR + mA];
            uint32_t v0 = AS[(k0    ) * ASTR + mB];
            uint32_t v1 = AS[(k0 + 1) * ASTR + mB];
            uint32_t v2 = AS[(k0 + 8) * ASTR + mB];
            uint32_t v3 = AS[(k0 + 9) * ASTR + mB];
            uint32_t ahi[4], alo[4];
            ahi[0] = (u0 & 0xffffu) | (u1 << 16);
            alo[0] = (u0 >> 16)     | (u1 & 0xffff0000u);
            ahi[1] = (v0 & 0xffffu) | (v1 << 16);
            alo[1] = (v0 >> 16)     | (v1 & 0xffff0000u);
            ahi[2] = (u2 & 0xffffu) | (u3 << 16);
            alo[2] = (u2 >> 16)     | (u3 & 0xffff0000u);
            ahi[3] = (v2 & 0xffffu) | (v3 << 16);
            alo[3] = (v2 >> 16)     | (v3 & 0xffff0000u);

            int kbg = kh * 4 + kb;
#pragma unroll
            for (int nb = 0; nb < 16; nb++) {
                uint2 wh = WH[(kbg * 16 + nb) * 32 + lane];
                mma16816(acc[nb], ahi, wh.x, wh.y);   // Ahi * Bh
                mma16816(acc[nb], alo, wh.x, wh.y);   // Alo * Bh
            }
        }
        __syncthreads();
    }

    // Bias add. Lane owns cols nb*8 + (lane%4)*2 + {0,1}; rows mA (c0,c1), mB (c2,c3)
    int col0 = (lane & 3) * 2;
#pragma unroll
    for (int nb = 0; nb < 16; nb++) {
        float b0 = bs[nb * 8 + col0];
        float b1 = bs[nb * 8 + col0 + 1];
        acc[nb][0] += b0; acc[nb][1] += b1;
        acc[nb][2] += b0; acc[nb][3] += b1;
    }

    // Softmax per row; reduction across the 4 lanes of each quad
    float mxA = -3.4e38f, mxB = -3.4e38f;
#pragma unroll
    for (int nb = 0; nb < 16; nb++) {
        mxA = fmaxf(mxA, fmaxf(acc[nb][0], acc[nb][1]));
        mxB = fmaxf(mxB, fmaxf(acc[nb][2], acc[nb][3]));
    }
#pragma unroll
    for (int o = 1; o <= 2; o <<= 1) {
        mxA = fmaxf(mxA, __shfl_xor_sync(0xffffffffu, mxA, o));
        mxB = fmaxf(mxB, __shfl_xor_sync(0xffffffffu, mxB, o));
    }
    float sA = 0.0f, sB = 0.0f;
#pragma unroll
    for (int nb = 0; nb < 16; nb++) {
        acc[nb][0] = __expf(acc[nb][0] - mxA);
        acc[nb][1] = __expf(acc[nb][1] - mxA);
        acc[nb][2] = __expf(acc[nb][2] - mxB);
        acc[nb][3] = __expf(acc[nb][3] - mxB);
        sA += acc[nb][0] + acc[nb][1];
        sB += acc[nb][2] + acc[nb][3];
    }
#pragma unroll
    for (int o = 1; o <= 2; o <<= 1) {
        sA += __shfl_xor_sync(0xffffffffu, sA, o);
        sB += __shfl_xor_sync(0xffffffffu, sB, o);
    }
    float invA = 1.0f / sA, invB = 1.0f / sB;
#pragma unroll
    for (int nb = 0; nb < 16; nb++) {
        acc[nb][0] *= invA; acc[nb][1] *= invA;
        acc[nb][2] *= invB; acc[nb][3] *= invB;
    }

    // Inverted gather: write each row to every k in its bucket (float2 stores)
    {
        int pA = p0 + mA;
        int nA = min(g_cnt[pA], BCAP);
        for (int j = 0; j < nA; j++) {
            int k = g_bucket[(size_t)pA * BCAP + j];
            float2* o = (float2*)(out + (size_t)k * NCLS);
#pragma unroll
            for (int nb = 0; nb < 16; nb++)
                o[nb * 4 + (lane & 3)] = make_float2(acc[nb][0], acc[nb][1]);
        }
        int pB = p0 + mB;
        int nB = min(g_cnt[pB], BCAP);
        for (int j = 0; j < nB; j++) {
            int k = g_bucket[(size_t)pB * BCAP + j];
            float2* o = (float2*)(out + (size_t)k * NCLS);
#pragma unroll
            for (int nb = 0; nb < 16; nb++)
                o[nb * 4 + (lane & 3)] = make_float2(acc[nb][2], acc[nb][3]);
        }
    }
}

// ---------------------------------------------------------------------------
// Launch
// ---------------------------------------------------------------------------
extern "C" void kernel_launch(void* const* d_in, const int* in_sizes, int n_in,
                              void* d_out, int out_size) {
    const float* gc   = (const float*)d_in[0];   // [1,128,512,512] f32
    const void*  cmap = d_in[1];                 // [1,131072] int64/int32
    const float* Wc   = (const float*)d_in[2];   // [128,128] f32
    const float* bc   = (const float*)d_in[3];   // [128] f32
    float*       out  = (float*)d_out;           // [131072,128] f32

    zero_convert_kernel<<<HW / 256, 256>>>(cmap);
    scatter_kernel<<<K / 256, 256>>>();
    prepW_kernel<<<32, 256>>>(Wc);

    cudaFuncSetAttribute(gemm_kernel,
                         cudaFuncAttributeMaxDynamicSharedMemorySize, SM_TOTAL);
    gemm_kernel<<<NTILES, 256, SM_TOTAL>>>(gc, bc, out);
}

// round 17
// speedup vs baseline: 2.0213x; 2.0213x over previous
#include <cuda_runtime.h>
#include <cuda_fp16.h>
#include <cstdint>
#include <cstring>

// ---------------------------------------------------------------------------
// Problem constants
// ---------------------------------------------------------------------------
static constexpr int C      = 128;          // emb dim (GEMM K)
static constexpr int NCLS   = 128;          // classes (GEMM N)
static constexpr int HW     = 262144;       // spatial positions (GEMM M total)
static constexpr int K      = 131072;       // gathered rows
static constexpr int TILE_M = 128;
static constexpr int NTILES = HW / TILE_M;  // 2048
static constexpr int BCAP   = 16;           // bucket capacity (Poisson(0.5): overflow ~1e-21)

// ---------------------------------------------------------------------------
// Device scratch (static — no runtime allocation)
// ---------------------------------------------------------------------------
__device__ int g_idx[K];                      // normalized int32 indices
__device__ int g_cnt[HW];                     // per-position multiplicity
__device__ int g_bucket[(size_t)HW * BCAP];   // inverted index (16 MB)
__device__ __align__(16) uint32_t g_Wf[8192]; // W fp16 frags, lane-ordered

// ---------------------------------------------------------------------------
// Warp MMA: m16n8k16, fp16 x fp16 -> fp32
// ---------------------------------------------------------------------------
__device__ __forceinline__ void mma16816(float* c, const uint32_t* a,
                                         uint32_t b0, uint32_t b1) {
    asm volatile(
        "mma.sync.aligned.m16n8k16.row.col.f32.f16.f16.f32 "
        "{%0,%1,%2,%3}, {%4,%5,%6,%7}, {%8,%9}, {%0,%1,%2,%3};"
        : "+f"(c[0]), "+f"(c[1]), "+f"(c[2]), "+f"(c[3])
        : "r"(a[0]), "r"(a[1]), "r"(a[2]), "r"(a[3]), "r"(b0), "r"(b1));
}

// fp16 hi/lo pair pack: (hi(f0),hi(f1)) and (lo(f0),lo(f1)) as fp16x2 words
__device__ __forceinline__ void pack_pair(float a0, float a1,
                                          uint32_t& hi, uint32_t& lo) {
    __half h0 = __float2half(a0);
    __half h1 = __float2half(a1);
    __half l0 = __float2half(a0 - __half2float(h0));
    __half l1 = __float2half(a1 - __half2float(h1));
    unsigned short h0b, h1b, l0b, l1b;
    memcpy(&h0b, &h0, 2); memcpy(&h1b, &h1, 2);
    memcpy(&l0b, &l0, 2); memcpy(&l1b, &l1, 2);
    hi = (uint32_t)h0b | ((uint32_t)h1b << 16);
    lo = (uint32_t)l0b | ((uint32_t)l1b << 16);
}

// ---------------------------------------------------------------------------
// Kernel 1: zero counters + normalize index dtype (int64-or-int32) to int32
// ---------------------------------------------------------------------------
__global__ void zero_convert_kernel(const void* __restrict__ raw) {
    int t = blockIdx.x * 256 + threadIdx.x;      // HW threads
    g_cnt[t] = 0;
    if (t < K) {
        const int* i32 = (const int*)raw;
        bool is64 = true;
#pragma unroll
        for (int j = 0; j < 32; j++)
            if (i32[2 * j + 1] != 0) is64 = false;
        g_idx[t] = is64 ? i32[2 * t] : i32[t];
    }
}

// ---------------------------------------------------------------------------
// Kernel 2: scatter k into fixed-capacity buckets
// ---------------------------------------------------------------------------
__global__ void scatter_kernel() {
    int k = blockIdx.x * 256 + threadIdx.x;
    int p = g_idx[k];
    int s = atomicAdd(&g_cnt[p], 1);
    if (s < BCAP) g_bucket[(size_t)p * BCAP + s] = k;
}

// ---------------------------------------------------------------------------
// Kernel 3: W -> fp16 mma-fragment-ordered array.
// Entry t = ((kb*16+nb)*32 + lane)*2 + reg.
//   n = nb*8 + lane/4 ; k = kb*16 + (lane%4)*2 + reg*8 ; packs W[n][k],W[n][k+1]
// ---------------------------------------------------------------------------
__global__ void prepW_kernel(const float* __restrict__ W) {
    int t = blockIdx.x * 256 + threadIdx.x;      // 8192
    int r  = t & 1;
    int l  = (t >> 1) & 31;
    int f  = t >> 6;                              // kb*16+nb
    int kb = f >> 4, nb = f & 15;
    int n = nb * 8 + (l >> 2);
    int k = kb * 16 + (l & 3) * 2 + r * 8;
    __half h0 = __float2half(W[n * C + k]);
    __half h1 = __float2half(W[n * C + k + 1]);
    unsigned short h0b, h1b;
    memcpy(&h0b, &h0, 2); memcpy(&h1b, &h1, 2);
    g_Wf[t] = (uint32_t)h0b | ((uint32_t)h1b << 16);
}

// ---------------------------------------------------------------------------
// Fused dense GEMM + softmax + inverted-gather epilogue — A-in-registers.
// 8 warps x (16 m x 128 n). A never touches smem: each thread LDGs its own
// 8 floats per k-block (1-deep prefetch), packs fp16 hi/lo, feeds 2 MMA
// passes (A exact, B fp16 => rel_err ~1.3e-4, validated R13).
// No barriers in the mainloop. smem = W frags 32KB + bias.
// ---------------------------------------------------------------------------
static constexpr int SM_W    = 0;                   // 32768
static constexpr int SM_BIAS = 32768;               // 512
static constexpr int SM_TOTAL = 33280;

__global__ void __launch_bounds__(256, 2)
gemm_kernel(const float* __restrict__ gc,
            const float* __restrict__ bias,
            float* __restrict__ out) {
    extern __shared__ unsigned char smem[];
    const uint2* WF = (const uint2*)(smem + SM_W);
    float* bs = (float*)(smem + SM_BIAS);

    int tid  = threadIdx.x;
    int lane = tid & 31;
    int warp = tid >> 5;
    int p0   = blockIdx.x * TILE_M;
    int q    = lane >> 2;                // 0..7
    int t    = lane & 3;                 // 0..3

    // Stage W fragment array + bias
    {
        const int4* sw = (const int4*)g_Wf;              // 2048 int4
        int4* dw = (int4*)(smem + SM_W);
#pragma unroll
        for (int i = 0; i < 8; i++)
            dw[tid + i * 256] = sw[tid + i * 256];
        if (tid < NCLS) bs[tid] = bias[tid];
    }
    __syncthreads();

    // Per-thread A source pointer: row rA = p0 + warp*16 + q, channel base t*2.
    // Per k-block offsets: 0, HW, 8HW, 9HW (channels c0,c0+1,c0+8,c0+9),
    // each also at +8 floats for row rB = rA + 8.
    const float* ap = gc + (size_t)(t * 2) * HW + p0 + warp * 16 + q;

    float acc[16][4];
#pragma unroll
    for (int nb = 0; nb < 16; nb++)
#pragma unroll
        for (int j = 0; j < 4; j++) acc[nb][j] = 0.0f;

    // cf layout: [0]=(c0,rA) [1]=(c1,rA) [2]=(c8,rA) [3]=(c9,rA)
    //            [4]=(c0,rB) [5]=(c1,rB) [6]=(c8,rB) [7]=(c9,rB)
    float cf[8], nf[8];
#pragma unroll
    for (int j = 0; j < 2; j++) {
        cf[0 + j * 4] = __ldg(ap + 0 * HW + j * 8);
        cf[1 + j * 4] = __ldg(ap + 1 * HW + j * 8);
        cf[2 + j * 4] = __ldg(ap + 8 * HW + j * 8);
        cf[3 + j * 4] = __ldg(ap + 9 * HW + j * 8);
    }

#pragma unroll
    for (int kb = 0; kb < 8; kb++) {
        // Prefetch next k-block (independent; covered by this block's MMAs)
        if (kb < 7) {
            const float* np = ap + (size_t)((kb + 1) * 16) * HW;
#pragma unroll
            for (int j = 0; j < 2; j++) {
                nf[0 + j * 4] = __ldg(np + 0 * HW + j * 8);
                nf[1 + j * 4] = __ldg(np + 1 * HW + j * 8);
                nf[2 + j * 4] = __ldg(np + 8 * HW + j * 8);
                nf[3 + j * 4] = __ldg(np + 9 * HW + j * 8);
            }
        }

        // Build A fragments (fp16 hi/lo), standard m16n8k16 layout
        uint32_t ahi[4], alo[4];
        pack_pair(cf[0], cf[1], ahi[0], alo[0]);   // row rA, k0..k0+1
        pack_pair(cf[4], cf[5], ahi[1], alo[1]);   // row rB, k0..k0+1
        pack_pair(cf[2], cf[3], ahi[2], alo[2]);   // row rA, k0+8..k0+9
        pack_pair(cf[6], cf[7], ahi[3], alo[3]);   // row rB, k0+8..k0+9

#pragma unroll
        for (int nb = 0; nb < 16; nb++) {
            uint2 w = WF[(kb * 16 + nb) * 32 + lane];
            mma16816(acc[nb], ahi, w.x, w.y);      // Ahi * B
            mma16816(acc[nb], alo, w.x, w.y);      // Alo * B
        }

#pragma unroll
        for (int j = 0; j < 8; j++) cf[j] = nf[j];
    }

    // Bias add. Lane owns cols nb*8 + t*2 + {0,1}; rows rA (c0,c1), rB (c2,c3)
    int col0 = t * 2;
#pragma unroll
    for (int nb = 0; nb < 16; nb++) {
        float b0 = bs[nb * 8 + col0];
        float b1 = bs[nb * 8 + col0 + 1];
        acc[nb][0] += b0; acc[nb][1] += b1;
        acc[nb][2] += b0; acc[nb][3] += b1;
    }

    // Softmax per row; reduction across the 4 lanes of each quad
    float mxA = -3.4e38f, mxB = -3.4e38f;
#pragma unroll
    for (int nb = 0; nb < 16; nb++) {
        mxA = fmaxf(mxA, fmaxf(acc[nb][0], acc[nb][1]));
        mxB = fmaxf(mxB, fmaxf(acc[nb][2], acc[nb][3]));
    }
#pragma unroll
    for (int o = 1; o <= 2; o <<= 1) {
        mxA = fmaxf(mxA, __shfl_xor_sync(0xffffffffu, mxA, o));
        mxB = fmaxf(mxB, __shfl_xor_sync(0xffffffffu, mxB, o));
    }
    float sA = 0.0f, sB = 0.0f;
#pragma unroll
    for (int nb = 0; nb < 16; nb++) {
        acc[nb][0] = __expf(acc[nb][0] - mxA);
        acc[nb][1] = __expf(acc[nb][1] - mxA);
        acc[nb][2] = __expf(acc[nb][2] - mxB);
        acc[nb][3] = __expf(acc[nb][3] - mxB);
        sA += acc[nb][0] + acc[nb][1];
        sB += acc[nb][2] + acc[nb][3];
    }
#pragma unroll
    for (int o = 1; o <= 2; o <<= 1) {
        sA += __shfl_xor_sync(0xffffffffu, sA, o);
        sB += __shfl_xor_sync(0xffffffffu, sB, o);
    }
    float invA = 1.0f / sA, invB = 1.0f / sB;
#pragma unroll
    for (int nb = 0; nb < 16; nb++) {
        acc[nb][0] *= invA; acc[nb][1] *= invA;
        acc[nb][2] *= invB; acc[nb][3] *= invB;
    }

    // Inverted gather: write each row to every k in its bucket (float2 stores)
    int mA = warp * 16 + q;
    {
        int pA = p0 + mA;
        int nA = min(g_cnt[pA], BCAP);
        for (int j = 0; j < nA; j++) {
            int k = g_bucket[(size_t)pA * BCAP + j];
            float2* o = (float2*)(out + (size_t)k * NCLS);
#pragma unroll
            for (int nb = 0; nb < 16; nb++)
                o[nb * 4 + t] = make_float2(acc[nb][0], acc[nb][1]);
        }
        int pB = pA + 8;
        int nB = min(g_cnt[pB], BCAP);
        for (int j = 0; j < nB; j++) {
            int k = g_bucket[(size_t)pB * BCAP + j];
            float2* o = (float2*)(out + (size_t)k * NCLS);
#pragma unroll
            for (int nb = 0; nb < 16; nb++)
                o[nb * 4 + t] = make_float2(acc[nb][2], acc[nb][3]);
        }
    }
}

// ---------------------------------------------------------------------------
// Launch
// ---------------------------------------------------------------------------
extern "C" void kernel_launch(void* const* d_in, const int* in_sizes, int n_in,
                              void* d_out, int out_size) {
    const float* gc   = (const float*)d_in[0];   // [1,128,512,512] f32
    const void*  cmap = d_in[1];                 // [1,131072] int64/int32
    const float* Wc   = (const float*)d_in[2];   // [128,128] f32
    const float* bc   = (const float*)d_in[3];   // [128] f32
    float*       out  = (float*)d_out;           // [131072,128] f32

    zero_convert_kernel<<<HW / 256, 256>>>(cmap);
    scatter_kernel<<<K / 256, 256>>>();
    prepW_kernel<<<32, 256>>>(Wc);

    cudaFuncSetAttribute(gemm_kernel,
                         cudaFuncAttributeMaxDynamicSharedMemorySize, SM_TOTAL);
    gemm_kernel<<<NTILES, 256, SM_TOTAL>>>(gc, bc, out);
}